// round 9
// baseline (speedup 1.0000x reference)
#include <cuda_runtime.h>
#include <cuda_bf16.h>

#define BATCH    4
#define NBOX     8192
#define TILE     128
#define THREADS  256
#define T_TILES  (NBOX / TILE)                  // 64
#define NPAIRS   (T_TILES * (T_TILES + 1) / 2)  // 2080

// Scratch (no device allocs): per-slot partial adjusted sums + reduced vector.
__device__ float g_part2[T_TILES][BATCH * NBOX];   // 8 MB
__device__ float g_adj[BATCH * NBOX];              // 128 KB

// ---------------------------------------------------------------------------
// Symmetric tile-pair kernel. Tile pair (ti <= tj), 128x128 entries.
// 256 threads = 16 row-groups x 16 col-groups; each thread owns an 8x8
// sub-block: 8 row accumulators + 8 col accumulators in registers.
// w(i,j) computed ONCE; credited to row i (w*s_j) and col j (w*s_i).
// Diag tiles: strict upper triangle + exact self term exp(-2)*s_i.
// ---------------------------------------------------------------------------
template<bool DIAG>
__device__ __forceinline__ void tile_body(
    const float4* __restrict__ sboxI, const float2* __restrict__ sasI,
    const float4* __restrict__ sboxJ, const float2* __restrict__ sasJ,
    int rg, int cg, float* __restrict__ racc, float* __restrict__ cacc)
{
    // exp(-iou/0.5) = exp2(iou * (-2/ln2))
    const float C = -2.8853900817779268f;

    float4 rb[8]; float ra[8]; float rs[8];
    #pragma unroll
    for (int r = 0; r < 8; ++r) {
        int ir = rg * 8 + r;
        rb[r] = sboxI[ir];
        float2 t = sasI[ir];
        ra[r] = t.x; rs[r] = t.y;
    }

    #pragma unroll
    for (int c = 0; c < 8; ++c) {
        const int jc = cg * 8 + c;
        const float4 jb = sboxJ[jc];
        const float2 ja = sasJ[jc];
        float ca = 0.0f;
        #pragma unroll
        for (int r = 0; r < 8; ++r) {
            float iw = fmaxf(fminf(rb[r].z, jb.z) - fmaxf(rb[r].x, jb.x), 0.0f);
            float ih = fmaxf(fminf(rb[r].w, jb.w) - fmaxf(rb[r].y, jb.y), 0.0f);
            float inter = iw * ih;
            float uni   = (ra[r] + ja.x) - inter;
            float rc; asm("rcp.approx.ftz.f32 %0, %1;" : "=f"(rc) : "f"(uni));
            float t = (inter * C) * rc;
            float w; asm("ex2.approx.ftz.f32 %0, %1;" : "=f"(w) : "f"(t));
            if (DIAG) w = (jc > rg * 8 + r) ? w : 0.0f;   // strict upper only
            racc[r] = fmaf(w, ja.y, racc[r]);
            ca      = fmaf(w, rs[r], ca);
        }
        cacc[c] = __fadd_rn(cacc[c], ca);
    }
}

__global__ __launch_bounds__(THREADS)
void symm_kernel(const float* __restrict__ boxes,
                 const float* __restrict__ scores)
{
    const int b = blockIdx.y;

    // triangular decode: pair index -> (ti, tj), ti <= tj
    const int p = blockIdx.x;
    int ti = (int)((2.0f * T_TILES + 1.0f
                    - sqrtf((2.0f * T_TILES + 1.0f) * (2.0f * T_TILES + 1.0f) - 8.0f * p)) * 0.5f);
    ti = ti < 0 ? 0 : (ti >= T_TILES ? T_TILES - 1 : ti);
    #pragma unroll 1
    while (ti > 0 && (ti * (2 * T_TILES - ti + 1)) / 2 > p) --ti;
    #pragma unroll 1
    while (((ti + 1) * (2 * T_TILES - ti)) / 2 <= p) ++ti;
    const int tj = ti + (p - (ti * (2 * T_TILES - ti + 1)) / 2);
    const bool diag = (ti == tj);

    __shared__ float4 sboxI[TILE];
    __shared__ float2 sasI[TILE];
    __shared__ float4 sboxJ[TILE];
    __shared__ float2 sasJ[TILE];
    __shared__ float  red[TILE * 17];   // 16-way reduce buffer (padded)

    const float4* __restrict__ box4 = reinterpret_cast<const float4*>(boxes) + (size_t)b * NBOX;
    const float*  __restrict__ sc   = scores + (size_t)b * NBOX;

    const int tid   = threadIdx.x;
    const int rg    = tid >> 4;      // 0..15
    const int cg    = tid & 15;      // 0..15
    const int ibase = ti * TILE;
    const int jbase = tj * TILE;

    // stage both tiles
    if (tid < TILE) {
        float4 v = box4[ibase + tid];
        sboxI[tid] = v;
        sasI[tid]  = make_float2((v.z - v.x) * (v.w - v.y), sc[ibase + tid]);
    } else {
        int k = tid - TILE;
        float4 v = box4[jbase + k];
        sboxJ[k] = v;
        sasJ[k]  = make_float2((v.z - v.x) * (v.w - v.y), sc[jbase + k]);
    }
    __syncthreads();

    float racc[8] = {0,0,0,0,0,0,0,0};
    float cacc[8] = {0,0,0,0,0,0,0,0};

    if (diag) tile_body<true >(sboxI, sasI, sboxJ, sasJ, rg, cg, racc, cacc);
    else      tile_body<false>(sboxI, sasI, sboxJ, sasJ, rg, cg, racc, cacc);

    // ---- row reduce: sum over 16 col-groups (fixed order -> deterministic) ----
    #pragma unroll
    for (int r = 0; r < 8; ++r)
        red[(rg * 8 + r) * 17 + cg] = racc[r];
    __syncthreads();

    float rowsum = 0.0f;
    if (tid < TILE) {
        rowsum = red[tid * 17 + 0];
        #pragma unroll
        for (int k = 1; k < 16; ++k)
            rowsum = __fadd_rn(rowsum, red[tid * 17 + k]);
    }
    __syncthreads();

    // ---- col reduce: sum over 16 row-groups ----
    #pragma unroll
    for (int c = 0; c < 8; ++c)
        red[(cg * 8 + c) * 17 + rg] = cacc[c];
    __syncthreads();

    float colsum = 0.0f;
    if (tid < TILE) {
        colsum = red[tid * 17 + 0];
        #pragma unroll
        for (int k = 1; k < 16; ++k)
            colsum = __fadd_rn(colsum, red[tid * 17 + k]);
    }

    // ---- store partials: unique (slot, index) writer per CTA ----
    if (tid < TILE) {
        if (diag) {
            const float E2 = 0.13533528323661270f;   // exp(-2) self term
            float v = __fadd_rn(__fadd_rn(rowsum, colsum), E2 * sasI[tid].y);
            g_part2[ti][(size_t)b * NBOX + ibase + tid] = v;
        } else {
            g_part2[tj][(size_t)b * NBOX + ibase + tid] = rowsum;   // rows of tile ti
            g_part2[ti][(size_t)b * NBOX + jbase + tid] = colsum;   // cols of tile tj
        }
    }
}

// ---------------------------------------------------------------------------
// Reduce the 64 slots (fixed order, Kahan) into g_adj. float4 loads.
// ---------------------------------------------------------------------------
__global__ __launch_bounds__(THREADS)
void reduce_kernel()
{
    const int idx = blockIdx.x * THREADS + threadIdx.x;  // [0, BATCH*NBOX/4)
    float4 a = reinterpret_cast<const float4*>(g_part2[0])[idx];
    float4 comp = make_float4(0.f, 0.f, 0.f, 0.f);
    #pragma unroll 1
    for (int s = 1; s < T_TILES; ++s) {
        float4 v = reinterpret_cast<const float4*>(g_part2[s])[idx];
        float y, t;
        y = __fsub_rn(v.x, comp.x); t = __fadd_rn(a.x, y); comp.x = __fsub_rn(__fsub_rn(t, a.x), y); a.x = t;
        y = __fsub_rn(v.y, comp.y); t = __fadd_rn(a.y, y); comp.y = __fsub_rn(__fsub_rn(t, a.y), y); a.y = t;
        y = __fsub_rn(v.z, comp.z); t = __fadd_rn(a.z, y); comp.z = __fsub_rn(__fsub_rn(t, a.z), y); a.z = t;
        y = __fsub_rn(v.w, comp.w); t = __fadd_rn(a.w, y); comp.w = __fsub_rn(__fsub_rn(t, a.w), y); a.w = t;
    }
    reinterpret_cast<float4*>(g_adj)[idx] = a;
}

// ---------------------------------------------------------------------------
// Per-batch softmax(adjusted) and weighted box average.
// ---------------------------------------------------------------------------
__global__ __launch_bounds__(1024)
void softmax_out_kernel(const float* __restrict__ boxes,
                        float* __restrict__ out)
{
    const int b = blockIdx.x;
    const int t = threadIdx.x;
    const float*  __restrict__ adj  = g_adj + b * NBOX;
    const float4* __restrict__ box4 = reinterpret_cast<const float4*>(boxes) + (size_t)b * NBOX;

    __shared__ float sred[32];
    __shared__ float s5[5][32];

    // ---- block max ----
    float m = -3.4e38f;
    for (int i = t; i < NBOX; i += 1024) m = fmaxf(m, adj[i]);
    #pragma unroll
    for (int o = 16; o; o >>= 1) m = fmaxf(m, __shfl_xor_sync(0xffffffffu, m, o));
    if ((t & 31) == 0) sred[t >> 5] = m;
    __syncthreads();
    if (t < 32) {
        float v = sred[t];
        #pragma unroll
        for (int o = 16; o; o >>= 1) v = fmaxf(v, __shfl_xor_sync(0xffffffffu, v, o));
        if (t == 0) sred[0] = v;
    }
    __syncthreads();
    m = sred[0];

    // ---- weighted sums ----
    float se = 0.f, sx1 = 0.f, sy1 = 0.f, sx2 = 0.f, sy2 = 0.f;
    for (int i = t; i < NBOX; i += 1024) {
        float e = __expf(adj[i] - m);
        float4 bx = box4[i];
        se  += e;
        sx1 = fmaf(e, bx.x, sx1);
        sy1 = fmaf(e, bx.y, sy1);
        sx2 = fmaf(e, bx.z, sx2);
        sy2 = fmaf(e, bx.w, sy2);
    }
    #pragma unroll
    for (int o = 16; o; o >>= 1) {
        se  += __shfl_xor_sync(0xffffffffu, se,  o);
        sx1 += __shfl_xor_sync(0xffffffffu, sx1, o);
        sy1 += __shfl_xor_sync(0xffffffffu, sy1, o);
        sx2 += __shfl_xor_sync(0xffffffffu, sx2, o);
        sy2 += __shfl_xor_sync(0xffffffffu, sy2, o);
    }
    if ((t & 31) == 0) {
        int w = t >> 5;
        s5[0][w] = se; s5[1][w] = sx1; s5[2][w] = sy1; s5[3][w] = sx2; s5[4][w] = sy2;
    }
    __syncthreads();
    if (t < 32) {
        float a0 = s5[0][t], a1 = s5[1][t], a2 = s5[2][t], a3 = s5[3][t], a4 = s5[4][t];
        #pragma unroll
        for (int o = 16; o; o >>= 1) {
            a0 += __shfl_xor_sync(0xffffffffu, a0, o);
            a1 += __shfl_xor_sync(0xffffffffu, a1, o);
            a2 += __shfl_xor_sync(0xffffffffu, a2, o);
            a3 += __shfl_xor_sync(0xffffffffu, a3, o);
            a4 += __shfl_xor_sync(0xffffffffu, a4, o);
        }
        if (t == 0) {
            float inv = 1.0f / a0;   // exact divide for final precision
            out[b * 4 + 0] = a1 * inv;
            out[b * 4 + 1] = a2 * inv;
            out[b * 4 + 2] = a3 * inv;
            out[b * 4 + 3] = a4 * inv;
        }
    }
}

// ---------------------------------------------------------------------------
extern "C" void kernel_launch(void* const* d_in, const int* in_sizes, int n_in,
                              void* d_out, int out_size)
{
    const float* boxes  = (const float*)d_in[0];
    const float* scores = (const float*)d_in[1];
    // Defensive: metadata order should be (boxes, scores); swap if sizes say otherwise.
    if (n_in >= 2 && in_sizes[0] == BATCH * NBOX && in_sizes[1] == BATCH * NBOX * 4) {
        const float* tmp = boxes; boxes = scores; scores = tmp;
    }
    float* out = (float*)d_out;

    symm_kernel<<<dim3(NPAIRS, BATCH), THREADS>>>(boxes, scores);
    reduce_kernel<<<(BATCH * NBOX / 4) / THREADS, THREADS>>>();
    softmax_out_kernel<<<BATCH, 1024>>>(boxes, out);
}

// round 10
// speedup vs baseline: 1.8971x; 1.8971x over previous
#include <cuda_runtime.h>
#include <cuda_bf16.h>

#define BATCH    4
#define NBOX     8192
#define TILE     128
#define THREADS  256
#define T_TILES  (NBOX / TILE)                  // 64
#define NPAIRS   (T_TILES * (T_TILES + 1) / 2)  // 2080

// Scratch (no device allocs): per-slot partial adjusted sums + reduced vector.
__device__ float g_part2[T_TILES][BATCH * NBOX];   // 8 MB
__device__ float g_adj[BATCH * NBOX];              // 128 KB
__device__ float g_pmax[32];                       // per-reduce-CTA max
__device__ float g_p5[32][5];                      // per-softpart-CTA partial sums

// ---------------------------------------------------------------------------
// Kernel 1: symmetric tile-pair kernel. Tile pair (ti <= tj), 128x128 entries.
// 256 threads = 16 row-groups x 16 col-groups; each thread owns an 8x8
// sub-block. w(i,j) computed ONCE; credited to row i (w*s_j) and col j (w*s_i).
// Column iteration order is rotated per-thread ((c+cg)&7) so LDS of the j-tile
// is bank-conflict-free; rotation only affects addresses, never register
// array indexing.
// ---------------------------------------------------------------------------
template<bool DIAG>
__device__ __forceinline__ void tile_body(
    const float4* __restrict__ sboxI, const float2* __restrict__ sasI,
    const float4* __restrict__ sboxJ, const float2* __restrict__ sasJ,
    int rg, int cg, float* __restrict__ racc, float* __restrict__ cacc)
{
    // exp(-iou/0.5) = exp2(iou * (-2/ln2))
    const float C = -2.8853900817779268f;

    float4 rb[8]; float ra[8]; float rs[8];
    #pragma unroll
    for (int r = 0; r < 8; ++r) {
        int ir = rg * 8 + r;
        rb[r] = sboxI[ir];
        float2 t = sasI[ir];
        ra[r] = t.x; rs[r] = t.y;
    }

    #pragma unroll
    for (int c = 0; c < 8; ++c) {
        const int jc = cg * 8 + ((c + cg) & 7);   // rotated -> conflict-free LDS
        const float4 jb = sboxJ[jc];
        const float2 ja = sasJ[jc];
        float ca = 0.0f;
        #pragma unroll
        for (int r = 0; r < 8; ++r) {
            float iw = fmaxf(fminf(rb[r].z, jb.z) - fmaxf(rb[r].x, jb.x), 0.0f);
            float ih = fmaxf(fminf(rb[r].w, jb.w) - fmaxf(rb[r].y, jb.y), 0.0f);
            float inter = iw * ih;
            float uni   = (ra[r] + ja.x) - inter;
            float rc; asm("rcp.approx.ftz.f32 %0, %1;" : "=f"(rc) : "f"(uni));
            float t = (inter * C) * rc;
            float w; asm("ex2.approx.ftz.f32 %0, %1;" : "=f"(w) : "f"(t));
            if (DIAG) w = (jc > rg * 8 + r) ? w : 0.0f;   // strict upper only
            racc[r] = fmaf(w, ja.y, racc[r]);
            ca      = fmaf(w, rs[r], ca);
        }
        cacc[c] = __fadd_rn(cacc[c], ca);   // cacc[c] <-> column jc (constant idx)
    }
}

__global__ __launch_bounds__(THREADS, 2)
void symm_kernel(const float* __restrict__ boxes,
                 const float* __restrict__ scores)
{
    const int b = blockIdx.y;

    // triangular decode: pair index -> (ti, tj), ti <= tj
    const int p = blockIdx.x;
    int ti = (int)((2.0f * T_TILES + 1.0f
                    - sqrtf((2.0f * T_TILES + 1.0f) * (2.0f * T_TILES + 1.0f) - 8.0f * p)) * 0.5f);
    ti = ti < 0 ? 0 : (ti >= T_TILES ? T_TILES - 1 : ti);
    #pragma unroll 1
    while (ti > 0 && (ti * (2 * T_TILES - ti + 1)) / 2 > p) --ti;
    #pragma unroll 1
    while (((ti + 1) * (2 * T_TILES - ti)) / 2 <= p) ++ti;
    const int tj = ti + (p - (ti * (2 * T_TILES - ti + 1)) / 2);
    const bool diag = (ti == tj);

    __shared__ float4 sboxI[TILE];
    __shared__ float2 sasI[TILE];
    __shared__ float4 sboxJ[TILE];
    __shared__ float2 sasJ[TILE];
    __shared__ float  red[TILE * 17];   // 16-way reduce buffer (padded)

    const float4* __restrict__ box4 = reinterpret_cast<const float4*>(boxes) + (size_t)b * NBOX;
    const float*  __restrict__ sc   = scores + (size_t)b * NBOX;

    const int tid   = threadIdx.x;
    const int rg    = tid >> 4;      // 0..15
    const int cg    = tid & 15;      // 0..15
    const int ibase = ti * TILE;
    const int jbase = tj * TILE;

    // stage both tiles
    if (tid < TILE) {
        float4 v = box4[ibase + tid];
        sboxI[tid] = v;
        sasI[tid]  = make_float2((v.z - v.x) * (v.w - v.y), sc[ibase + tid]);
    } else {
        int k = tid - TILE;
        float4 v = box4[jbase + k];
        sboxJ[k] = v;
        sasJ[k]  = make_float2((v.z - v.x) * (v.w - v.y), sc[jbase + k]);
    }
    __syncthreads();

    float racc[8] = {0,0,0,0,0,0,0,0};
    float cacc[8] = {0,0,0,0,0,0,0,0};

    if (diag) tile_body<true >(sboxI, sasI, sboxJ, sasJ, rg, cg, racc, cacc);
    else      tile_body<false>(sboxI, sasI, sboxJ, sasJ, rg, cg, racc, cacc);

    // ---- row reduce: sum over 16 col-groups (fixed order -> deterministic) ----
    #pragma unroll
    for (int r = 0; r < 8; ++r)
        red[(rg * 8 + r) * 17 + cg] = racc[r];
    __syncthreads();

    float rowsum = 0.0f;
    if (tid < TILE) {
        rowsum = red[tid * 17 + 0];
        #pragma unroll
        for (int k = 1; k < 16; ++k)
            rowsum = __fadd_rn(rowsum, red[tid * 17 + k]);
    }
    __syncthreads();

    // ---- col reduce: sum over 16 row-groups (store at rotated column jc) ----
    #pragma unroll
    for (int c = 0; c < 8; ++c) {
        const int jc = cg * 8 + ((c + cg) & 7);
        red[jc * 17 + rg] = cacc[c];
    }
    __syncthreads();

    float colsum = 0.0f;
    if (tid < TILE) {
        colsum = red[tid * 17 + 0];
        #pragma unroll
        for (int k = 1; k < 16; ++k)
            colsum = __fadd_rn(colsum, red[tid * 17 + k]);
    }

    // ---- store partials: unique (slot, index) writer per CTA ----
    if (tid < TILE) {
        if (diag) {
            const float E2 = 0.13533528323661270f;   // exp(-2) self term
            float v = __fadd_rn(__fadd_rn(rowsum, colsum), E2 * sasI[tid].y);
            g_part2[ti][(size_t)b * NBOX + ibase + tid] = v;
        } else {
            g_part2[tj][(size_t)b * NBOX + ibase + tid] = rowsum;   // rows of tile ti
            g_part2[ti][(size_t)b * NBOX + jbase + tid] = colsum;   // cols of tile tj
        }
    }
}

// ---------------------------------------------------------------------------
// Kernel 2: reduce the 64 slots into g_adj (4 independent chains -> MLP,
// combined in fixed order -> deterministic) and emit per-CTA max.
// Grid: 32 CTAs x 256 threads, 1 float4 per thread. CTA k covers floats
// [k*1024, (k+1)*1024) -> 8 CTAs per batch.
// ---------------------------------------------------------------------------
__global__ __launch_bounds__(THREADS)
void reduce_kernel()
{
    const int idx = blockIdx.x * THREADS + threadIdx.x;  // [0, BATCH*NBOX/4)

    float4 a0 = reinterpret_cast<const float4*>(g_part2[0])[idx];
    float4 a1 = reinterpret_cast<const float4*>(g_part2[1])[idx];
    float4 a2 = reinterpret_cast<const float4*>(g_part2[2])[idx];
    float4 a3 = reinterpret_cast<const float4*>(g_part2[3])[idx];
    #pragma unroll 1
    for (int s = 4; s < T_TILES; s += 4) {
        float4 v0 = reinterpret_cast<const float4*>(g_part2[s + 0])[idx];
        float4 v1 = reinterpret_cast<const float4*>(g_part2[s + 1])[idx];
        float4 v2 = reinterpret_cast<const float4*>(g_part2[s + 2])[idx];
        float4 v3 = reinterpret_cast<const float4*>(g_part2[s + 3])[idx];
        a0.x = __fadd_rn(a0.x, v0.x); a0.y = __fadd_rn(a0.y, v0.y);
        a0.z = __fadd_rn(a0.z, v0.z); a0.w = __fadd_rn(a0.w, v0.w);
        a1.x = __fadd_rn(a1.x, v1.x); a1.y = __fadd_rn(a1.y, v1.y);
        a1.z = __fadd_rn(a1.z, v1.z); a1.w = __fadd_rn(a1.w, v1.w);
        a2.x = __fadd_rn(a2.x, v2.x); a2.y = __fadd_rn(a2.y, v2.y);
        a2.z = __fadd_rn(a2.z, v2.z); a2.w = __fadd_rn(a2.w, v2.w);
        a3.x = __fadd_rn(a3.x, v3.x); a3.y = __fadd_rn(a3.y, v3.y);
        a3.z = __fadd_rn(a3.z, v3.z); a3.w = __fadd_rn(a3.w, v3.w);
    }
    // fixed-order combine
    float4 a;
    a.x = __fadd_rn(__fadd_rn(a0.x, a1.x), __fadd_rn(a2.x, a3.x));
    a.y = __fadd_rn(__fadd_rn(a0.y, a1.y), __fadd_rn(a2.y, a3.y));
    a.z = __fadd_rn(__fadd_rn(a0.z, a1.z), __fadd_rn(a2.z, a3.z));
    a.w = __fadd_rn(__fadd_rn(a0.w, a1.w), __fadd_rn(a2.w, a3.w));
    reinterpret_cast<float4*>(g_adj)[idx] = a;

    // per-CTA max
    __shared__ float smax[8];
    float m = fmaxf(fmaxf(a.x, a.y), fmaxf(a.z, a.w));
    #pragma unroll
    for (int o = 16; o; o >>= 1) m = fmaxf(m, __shfl_xor_sync(0xffffffffu, m, o));
    if ((threadIdx.x & 31) == 0) smax[threadIdx.x >> 5] = m;
    __syncthreads();
    if (threadIdx.x == 0) {
        float mm = smax[0];
        #pragma unroll
        for (int w = 1; w < 8; ++w) mm = fmaxf(mm, smax[w]);
        g_pmax[blockIdx.x] = mm;
    }
}

// ---------------------------------------------------------------------------
// Kernel 3: partial softmax sums. Grid: 32 CTAs (8 per batch) x 256 threads.
// Each CTA handles 1024 boxes using the batch's global max (from g_pmax).
// ---------------------------------------------------------------------------
__global__ __launch_bounds__(THREADS)
void softpart_kernel(const float* __restrict__ boxes)
{
    const int cta = blockIdx.x;
    const int b   = cta >> 3;
    const int t   = threadIdx.x;

    // global max for this batch (8 per-CTA maxes, order-independent)
    float m = g_pmax[b * 8 + 0];
    #pragma unroll
    for (int k = 1; k < 8; ++k) m = fmaxf(m, g_pmax[b * 8 + k]);

    const int idx = cta * THREADS + t;    // float4 index into g_adj
    const float4 ad = reinterpret_cast<const float4*>(g_adj)[idx];
    const float4* __restrict__ box4 = reinterpret_cast<const float4*>(boxes);

    float e0 = __expf(ad.x - m);
    float e1 = __expf(ad.y - m);
    float e2 = __expf(ad.z - m);
    float e3 = __expf(ad.w - m);

    float4 b0 = box4[idx * 4 + 0];
    float4 b1 = box4[idx * 4 + 1];
    float4 b2 = box4[idx * 4 + 2];
    float4 b3 = box4[idx * 4 + 3];

    float se  = ((e0 + e1) + (e2 + e3));
    float sx1 = fmaf(e0, b0.x, fmaf(e1, b1.x, fmaf(e2, b2.x, e3 * b3.x)));
    float sy1 = fmaf(e0, b0.y, fmaf(e1, b1.y, fmaf(e2, b2.y, e3 * b3.y)));
    float sx2 = fmaf(e0, b0.z, fmaf(e1, b1.z, fmaf(e2, b2.z, e3 * b3.z)));
    float sy2 = fmaf(e0, b0.w, fmaf(e1, b1.w, fmaf(e2, b2.w, e3 * b3.w)));

    __shared__ float s5[5][8];
    #pragma unroll
    for (int o = 16; o; o >>= 1) {
        se  += __shfl_xor_sync(0xffffffffu, se,  o);
        sx1 += __shfl_xor_sync(0xffffffffu, sx1, o);
        sy1 += __shfl_xor_sync(0xffffffffu, sy1, o);
        sx2 += __shfl_xor_sync(0xffffffffu, sx2, o);
        sy2 += __shfl_xor_sync(0xffffffffu, sy2, o);
    }
    if ((t & 31) == 0) {
        int w = t >> 5;
        s5[0][w] = se; s5[1][w] = sx1; s5[2][w] = sy1; s5[3][w] = sx2; s5[4][w] = sy2;
    }
    __syncthreads();
    if (t < 5) {
        float a = s5[t][0];
        #pragma unroll
        for (int w = 1; w < 8; ++w) a = __fadd_rn(a, s5[t][w]);
        g_p5[cta][t] = a;
    }
}

// ---------------------------------------------------------------------------
// Kernel 4: final combine. Grid: 4 CTAs x 32 threads.
// ---------------------------------------------------------------------------
__global__ __launch_bounds__(32)
void final_kernel(float* __restrict__ out)
{
    const int b = blockIdx.x;
    if (threadIdx.x == 0) {
        float a[5] = {0.f, 0.f, 0.f, 0.f, 0.f};
        #pragma unroll
        for (int k = 0; k < 8; ++k)
            #pragma unroll
            for (int q = 0; q < 5; ++q)
                a[q] = __fadd_rn(a[q], g_p5[b * 8 + k][q]);
        float inv = 1.0f / a[0];
        out[b * 4 + 0] = a[1] * inv;
        out[b * 4 + 1] = a[2] * inv;
        out[b * 4 + 2] = a[3] * inv;
        out[b * 4 + 3] = a[4] * inv;
    }
}

// ---------------------------------------------------------------------------
extern "C" void kernel_launch(void* const* d_in, const int* in_sizes, int n_in,
                              void* d_out, int out_size)
{
    const float* boxes  = (const float*)d_in[0];
    const float* scores = (const float*)d_in[1];
    // Defensive: metadata order should be (boxes, scores); swap if sizes say otherwise.
    if (n_in >= 2 && in_sizes[0] == BATCH * NBOX && in_sizes[1] == BATCH * NBOX * 4) {
        const float* tmp = boxes; boxes = scores; scores = tmp;
    }
    float* out = (float*)d_out;

    symm_kernel<<<dim3(NPAIRS, BATCH), THREADS>>>(boxes, scores);
    reduce_kernel<<<(BATCH * NBOX / 4) / THREADS, THREADS>>>();
    softpart_kernel<<<32, THREADS>>>(boxes);
    final_kernel<<<BATCH, 32>>>(out);
}